// round 13
// baseline (speedup 1.0000x reference)
#include <cuda_runtime.h>

// ChannelPruner: out[b,o,h,w] = sum_c W[o,c] * x[b,c,h,w]
// SINGLE fused kernel, flat ILP=2 stream mapping (best measured).
// R13 change: 512-thread blocks -> half the blocks, so the compaction
// prologue + barrier is paid 6272x instead of 12544x. A 512-thread span
// over 392-thread planes touches <=3 planes; warps 0-2 each compact one
// candidate W row (ballot+popc, front-batched loads) into 3 smem slots.

#define N_CH   256
#define HW4    784               // 56*56/4 float4 per channel-plane
#define HALF4  392
#define BATCH  32
#define TOTAL4 (BATCH * N_CH * HW4)    // 6,422,528 float4
#define NTHREAD (TOTAL4 / 2)           // one thread per 2 outputs
#define TPB    512

__global__ void __launch_bounds__(TPB)
fused_prune_kernel(const float* __restrict__ x,
                   const float* __restrict__ w,
                   float* __restrict__ out) {
    __shared__ int   s_col[3][N_CH];
    __shared__ float s_val[3][N_CH];
    __shared__ int   s_nnz[3];

    const int base = blockIdx.x * TPB;
    const int idx  = base + threadIdx.x;            // 0..NTHREAD-1

    const int bo_first = base / HALF4;              // first plane this block touches
    const int warp = threadIdx.x >> 5;
    const int lane = threadIdx.x & 31;

    // --- warps 0..2: compact the (<=3) candidate W rows for this block ---
    if (warp < 3) {
        const int o_w = (bo_first + warp) & (N_CH - 1);   // harmless if past end
        const float* row = w + o_w * N_CH;

        float v[8];
        #pragma unroll
        for (int ch = 0; ch < 8; ++ch) v[ch] = row[ch * 32 + lane];  // MLP=8

        int off = 0;
        #pragma unroll
        for (int ch = 0; ch < 8; ++ch) {
            unsigned m = __ballot_sync(0xffffffffu, v[ch] != 0.0f);
            int pre = __popc(m & ((1u << lane) - 1u));
            if (v[ch] != 0.0f) {
                s_col[warp][off + pre] = ch * 32 + lane;
                s_val[warp][off + pre] = v[ch];
            }
            off += __popc(m);
        }
        if (lane == 0) s_nnz[warp] = off;
    }
    __syncthreads();

    // --- stream: 2 float4 per thread within one (b,o) plane ---
    const int p4 = idx % HALF4;       // umulhi magic division
    const int bo = idx / HALF4;
    const int b  = bo >> 8;
    const int slot = bo - bo_first;   // 0..2

    const int n = s_nnz[slot];
    const int*   cols = s_col[slot];
    const float* vals = s_val[slot];

    const float4* xb = (const float4*)x + b * (N_CH * HW4) + p4;

    float4 acc0 = make_float4(0.f, 0.f, 0.f, 0.f);
    float4 acc1 = acc0;

    for (int j = 0; j < n; ++j) {
        float v = vals[j];
        const float4* xc = xb + cols[j] * HW4;
        float4 xv0 = xc[0];           // independent loads -> MLP 2
        float4 xv1 = xc[HALF4];
        acc0.x = fmaf(v, xv0.x, acc0.x);
        acc0.y = fmaf(v, xv0.y, acc0.y);
        acc0.z = fmaf(v, xv0.z, acc0.z);
        acc0.w = fmaf(v, xv0.w, acc0.w);
        acc1.x = fmaf(v, xv1.x, acc1.x);
        acc1.y = fmaf(v, xv1.y, acc1.y);
        acc1.z = fmaf(v, xv1.z, acc1.z);
        acc1.w = fmaf(v, xv1.w, acc1.w);
    }

    float4* ob = (float4*)out + bo * HW4 + p4;
    ob[0]     = acc0;
    ob[HALF4] = acc1;
}

extern "C" void kernel_launch(void* const* d_in, const int* in_sizes, int n_in,
                              void* d_out, int out_size) {
    const float* x = (const float*)d_in[0];   // (32,256,56,56) fp32
    const float* w = (const float*)d_in[1];   // (256,256,1,1)  fp32
    float* out = (float*)d_out;

    fused_prune_kernel<<<NTHREAD / TPB, TPB>>>(x, w, out);   // 6272 blocks
}

// round 16
// speedup vs baseline: 1.0455x; 1.0455x over previous
#include <cuda_runtime.h>

// ChannelPruner: out[b,o,h,w] = sum_c W[o,c] * x[b,c,h,w]
// SINGLE fused kernel, flat ILP=2 mapping, 256-thread blocks (best measured).
// R14: warp-self-service compaction — NO smem, NO __syncthreads. Each warp
// spans <=2 (b,o) planes; per plane it loads the W row (front-batched),
// ballots the nonzero masks (warp-uniform), then walks set bits:
// col = ch*32+src, val = shfl(v[ch], src). Straddle warps (~8%) run the
// row loop twice with lane predication. Removes the 1.6us block-barrier
// prologue of the smem variant (R12: 28.4us kernel).

#define N_CH   256
#define HW4    784               // 56*56/4 float4 per channel-plane
#define HALF4  392
#define BATCH  32
#define TOTAL4 (BATCH * N_CH * HW4)    // 6,422,528 float4
#define NTHREAD (TOTAL4 / 2)           // one thread per 2 outputs

__global__ void __launch_bounds__(256)
fused_prune_kernel(const float* __restrict__ x,
                   const float* __restrict__ w,
                   float* __restrict__ out) {
    const unsigned FULL = 0xffffffffu;

    const int idx  = blockIdx.x * 256 + threadIdx.x;   // 0..NTHREAD-1
    const int lane = threadIdx.x & 31;

    const int p4 = idx % HALF4;       // umulhi magic division
    const int bo = idx / HALF4;
    const int o  = bo & (N_CH - 1);
    const int b  = bo >> 8;

    // distinct output rows this warp touches (consecutive bo -> <=2 rows,
    // and within a warp o uniquely identifies the plane)
    const int o_lo = __shfl_sync(FULL, o, 0);
    const int o_hi = __shfl_sync(FULL, o, 31);
    const int nrows = (o_hi != o_lo) ? 2 : 1;

    const float4* xb = (const float4*)x + b * (N_CH * HW4) + p4;

    float4 acc0 = make_float4(0.f, 0.f, 0.f, 0.f);
    float4 acc1 = acc0;

    for (int r = 0; r < nrows; ++r) {               // warp-uniform trip count
        const int  orow   = (r == 0) ? o_lo : o_hi;
        const bool active = (o == orow);

        const float* row = w + orow * N_CH;
        float v[8];
        #pragma unroll
        for (int ch = 0; ch < 8; ++ch)              // front-batched, MLP=8
            v[ch] = row[ch * 32 + lane];

        #pragma unroll
        for (int ch = 0; ch < 8; ++ch) {
            unsigned m = __ballot_sync(FULL, v[ch] != 0.0f);  // warp-uniform
            while (m) {                                       // uniform loop
                const int src = __ffs(m) - 1;
                m &= m - 1;
                const float val = __shfl_sync(FULL, v[ch], src);
                const int   col = ch * 32 + src;
                if (active) {
                    const float4* xc = xb + col * HW4;
                    float4 xv0 = xc[0];            // independent loads, MLP=2
                    float4 xv1 = xc[HALF4];
                    acc0.x = fmaf(val, xv0.x, acc0.x);
                    acc0.y = fmaf(val, xv0.y, acc0.y);
                    acc0.z = fmaf(val, xv0.z, acc0.z);
                    acc0.w = fmaf(val, xv0.w, acc0.w);
                    acc1.x = fmaf(val, xv1.x, acc1.x);
                    acc1.y = fmaf(val, xv1.y, acc1.y);
                    acc1.z = fmaf(val, xv1.z, acc1.z);
                    acc1.w = fmaf(val, xv1.w, acc1.w);
                }
            }
        }
    }

    float4* ob = (float4*)out + bo * HW4 + p4;
    ob[0]     = acc0;
    ob[HALF4] = acc1;
}

extern "C" void kernel_launch(void* const* d_in, const int* in_sizes, int n_in,
                              void* d_out, int out_size) {
    const float* x = (const float*)d_in[0];   // (32,256,56,56) fp32
    const float* w = (const float*)d_in[1];   // (256,256,1,1)  fp32
    float* out = (float*)d_out;

    fused_prune_kernel<<<NTHREAD / 256, 256>>>(x, w, out);   // 12544 blocks
}